// round 7
// baseline (speedup 1.0000x reference)
#include <cuda_runtime.h>
#include <cuda_bf16.h>
#include <cstdint>

#define NPTS 65536
#define HID  256
#define SLICE ((size_t)NPTS * HID)
#define NCH  13
#define NSG  (NPTS / 128)     // 512 sample groups

// fp32 GEMM-output buffers and bf16 hi/lo split activation buffers
static __device__ float          g_C  [(size_t)NCH * NPTS * HID];
static __device__ float          g_Cd [(size_t)3 * NPTS * HID];
static __device__ __nv_bfloat16  g_hiA[(size_t)NCH * NPTS * HID];
static __device__ __nv_bfloat16  g_loA[(size_t)NCH * NPTS * HID];
static __device__ __nv_bfloat16  g_hiB[(size_t)NCH * NPTS * HID];
static __device__ __nv_bfloat16  g_loB[(size_t)NCH * NPTS * HID];
// weight splits: slot 0=W2, 1=W3, 2=Wp1, 3=Wd1
static __device__ __nv_bfloat16  g_Whi[4 * 256 * 256];
static __device__ __nv_bfloat16  g_Wlo[4 * 256 * 256];
// decoupled-finisher counters (BSS zero; finishers reset to 0 after use)
static __device__ int            g_cnt[NSG];

// ---------------------------------------------------------------------------
// hi = truncate-to-bf16(f), lo = RN-bf16(f - hi)
// ---------------------------------------------------------------------------
__device__ __forceinline__ void store_hl(__nv_bfloat16* __restrict__ hi,
                                         __nv_bfloat16* __restrict__ lo,
                                         size_t idx, float f) {
    unsigned u = __float_as_uint(f);
    float h = __uint_as_float(u & 0xFFFF0000u);
    hi[idx] = __ushort_as_bfloat16((unsigned short)(u >> 16));
    lo[idx] = __float2bfloat16(f - h);
}

__device__ __forceinline__ __nv_bfloat16 trunc_bf(float f) {
    return __ushort_as_bfloat16((unsigned short)(__float_as_uint(f) >> 16));
}
__device__ __forceinline__ float trunc_res(float f) {
    return f - __uint_as_float(__float_as_uint(f) & 0xFFFF0000u);
}

__global__ void wconv_kernel(const float* __restrict__ w2,
                             const float* __restrict__ w3,
                             const float* __restrict__ wp1,
                             const float* __restrict__ wd1) {
    int e = blockIdx.x * blockDim.x + threadIdx.x;
    if (e >= 4 * 65536) return;
    int m = e >> 16;
    int l = e & 65535;
    const float* src = (m == 0) ? w2 : (m == 1) ? w3 : (m == 2) ? wp1 : wd1;
    store_hl(g_Whi, g_Wlo, (size_t)e, src[l]);
}

__global__ void layer1_kernel(const float* __restrict__ x,
                              const float* __restrict__ y,
                              const float* __restrict__ t,
                              const float* __restrict__ W1,
                              const float* __restrict__ b1) {
    int e = blockIdx.x * blockDim.x + threadIdx.x;
    if (e >= NPTS * HID) return;
    int n = e >> 8;
    int k = e & 255;
    float cx = W1[k * 3 + 0];
    float cy = W1[k * 3 + 1];
    float ct = W1[k * 3 + 2];
    float z = cx * x[n] + cy * y[n] + ct * t[n] + b1[k];
    float h = tanhf(z);
    float d = 1.0f - h * h;
    const size_t S = SLICE;
    store_hl(g_hiA, g_loA, e, h);
    store_hl(g_hiA, g_loA, S * 1 + e, d * cx);
    store_hl(g_hiA, g_loA, S * 2 + e, d * cy);
    store_hl(g_hiA, g_loA, S * 3 + e, d * ct);
    float m2 = -2.0f * h * d;
    store_hl(g_hiA, g_loA, S * 4 + e, m2 * cx * cx);
    store_hl(g_hiA, g_loA, S * 5 + e, m2 * cx * cy);
    store_hl(g_hiA, g_loA, S * 6 + e, m2 * cy * cy);
    store_hl(g_hiA, g_loA, S * 7 + e, m2 * cx * ct);
    store_hl(g_hiA, g_loA, S * 8 + e, m2 * cy * ct);
    float m3 = d * (6.0f * h * h - 2.0f);
    store_hl(g_hiA, g_loA, S * 9 + e,  m3 * cx * cx * cx);
    store_hl(g_hiA, g_loA, S * 10 + e, m3 * cx * cx * cy);
    store_hl(g_hiA, g_loA, S * 11 + e, m3 * cx * cy * cy);
    store_hl(g_hiA, g_loA, S * 12 + e, m3 * cy * cy * cy);
}

// ---------------------------------------------------------------------------
// Tensor-core GEMM (NT) + optional fused tanh-jet combine (decoupled finisher).
// C[m,n] = sum_k A[m,k]*W[n,k], K = N = 256. Block tile 128x128, 8 warps,
// K-chunk 32, cp.async double-buffer, ldmatrix. Accum Ah*Wh + Ah*Wl + Al*Wh.
// fuse=1: bx -> (sample group s = bx/13, channel ch = bx%13); the 26th block
// (13ch x 2 N-halves) to finish group s runs the jet combine for its 128
// samples, writing hiO/loO. fuse=0: bx linear; blocks >= nbig use W2_/C2_.
// ---------------------------------------------------------------------------
#define ROWB  80
#define ASTG  10240     // 128*80
#define SMSZ  (2*4*ASTG) // 81920

#define LDSM4(R, addr) \
    asm volatile("ldmatrix.sync.aligned.m8n8.x4.shared.b16 {%0,%1,%2,%3}, [%4];" \
                 : "=r"((R)[0]), "=r"((R)[1]), "=r"((R)[2]), "=r"((R)[3]) \
                 : "r"(addr))
#define CPA(dst, src) \
    asm volatile("cp.async.cg.shared.global [%0], [%1], 16;" :: "r"(dst), "l"(src))
#define CPC() asm volatile("cp.async.commit_group;")
#define CPW1() asm volatile("cp.async.wait_group 1;" ::: "memory")
#define CPW0() asm volatile("cp.async.wait_group 0;" ::: "memory")

__device__ __forceinline__ void mma_bf16(float* c, const unsigned* a,
                                         unsigned b0, unsigned b1) {
    asm volatile(
        "mma.sync.aligned.m16n8k16.row.col.f32.bf16.bf16.f32 "
        "{%0,%1,%2,%3}, {%4,%5,%6,%7}, {%8,%9}, {%0,%1,%2,%3};"
        : "+f"(c[0]), "+f"(c[1]), "+f"(c[2]), "+f"(c[3])
        : "r"(a[0]), "r"(a[1]), "r"(a[2]), "r"(a[3]), "r"(b0), "r"(b1));
}

__global__ void __launch_bounds__(256, 2)
gemm_v3(const __nv_bfloat16* __restrict__ Ahi,
        const __nv_bfloat16* __restrict__ Alo,
        const __nv_bfloat16* Whi_, const __nv_bfloat16* Wlo_, float* C_,
        const __nv_bfloat16* Whi2_, const __nv_bfloat16* Wlo2_, float* C2_,
        int nbig, int fuse,
        const float* __restrict__ bvec,
        __nv_bfloat16* __restrict__ hiO,
        __nv_bfloat16* __restrict__ loO) {
    extern __shared__ unsigned char sm[];
    const unsigned sb = (unsigned)__cvta_generic_to_shared(sm);

    int bx = blockIdx.x;
    const __nv_bfloat16* Whi = Whi_;
    const __nv_bfloat16* Wlo = Wlo_;
    float* C = C_;
    int sgrp = 0;
    size_t blockRow;
    if (fuse) {
        sgrp = bx / 13;
        int ch = bx - sgrp * 13;
        blockRow = (size_t)ch * NPTS + (size_t)sgrp * 128;
    } else {
        if (bx >= nbig) {            // appended second job (data head)
            bx -= nbig;
            Whi = Whi2_;
            Wlo = Wlo2_;
            C = C2_;
        }
        blockRow = (size_t)bx * 128;
    }

    const int tid  = threadIdx.x;
    const int lane = tid & 31;
    const int warp = tid >> 5;
    const int wm   = (warp & 3) * 32;
    const int wn   = (warp >> 2) * 64;
    const int blockN = blockIdx.y * 128;

    // loader: each thread stages 2 consecutive 16B chunks per array
    const int lr = tid >> 1;          // row 0..127
    const int lc = (tid & 1) * 2;     // chunk base 0 or 2 (of 4 per 32-k row)
    const __nv_bfloat16* gAh = Ahi + (blockRow + lr) * 256;
    const __nv_bfloat16* gAl = Alo + (blockRow + lr) * 256;
    const __nv_bfloat16* gWh = Whi + (size_t)(blockN + lr) * 256;
    const __nv_bfloat16* gWl = Wlo + (size_t)(blockN + lr) * 256;
    const unsigned sdst = sb + lr * ROWB + lc * 16;

    float acc[2][8][4];
#pragma unroll
    for (int i = 0; i < 2; i++)
#pragma unroll
        for (int j = 0; j < 8; j++)
#pragma unroll
            for (int l = 0; l < 4; l++) acc[i][j][l] = 0.0f;

#define ISSUE(stage, kc) do {                                                  \
        int koff = (kc) * 32;                                                  \
        unsigned d0 = sdst + (stage) * (4 * ASTG);                             \
        CPA(d0 + 0 * ASTG,      gAh + koff + lc * 8);                          \
        CPA(d0 + 0 * ASTG + 16, gAh + koff + lc * 8 + 8);                      \
        CPA(d0 + 1 * ASTG,      gAl + koff + lc * 8);                          \
        CPA(d0 + 1 * ASTG + 16, gAl + koff + lc * 8 + 8);                      \
        CPA(d0 + 2 * ASTG,      gWh + koff + lc * 8);                          \
        CPA(d0 + 2 * ASTG + 16, gWh + koff + lc * 8 + 8);                      \
        CPA(d0 + 3 * ASTG,      gWl + koff + lc * 8);                          \
        CPA(d0 + 3 * ASTG + 16, gWl + koff + lc * 8 + 8);                      \
        CPC();                                                                 \
    } while (0)

    ISSUE(0, 0);

    // fragment address components
    const int arow = wm + (lane & 15);
    const int acsel = (lane >> 4);
    const int brow = wn + (lane & 7) + ((lane >> 4) << 3);
    const int bcsel = (lane >> 3) & 1;

#pragma unroll 1
    for (int kc = 0; kc < 8; kc++) {
        if (kc < 7) ISSUE((kc + 1) & 1, kc + 1);
        if (kc < 7) { CPW1(); } else { CPW0(); }
        __syncthreads();

        const unsigned s0 = sb + (kc & 1) * (4 * ASTG);
#pragma unroll
        for (int step = 0; step < 2; step++) {
            unsigned aH[2][4], aL[2][4];
            const unsigned acol = (acsel + step * 2) * 16;
#pragma unroll
            for (int mt = 0; mt < 2; mt++) {
                LDSM4(aH[mt], s0 + 0 * ASTG + (arow + mt * 16) * ROWB + acol);
                LDSM4(aL[mt], s0 + 1 * ASTG + (arow + mt * 16) * ROWB + acol);
            }
            const unsigned bcol = (bcsel + step * 2) * 16;
#pragma unroll
            for (int ng = 0; ng < 4; ng++) {
                unsigned bh[4], bl[4];
                LDSM4(bh, s0 + 2 * ASTG + (brow + ng * 16) * ROWB + bcol);
                LDSM4(bl, s0 + 3 * ASTG + (brow + ng * 16) * ROWB + bcol);
#pragma unroll
                for (int mt = 0; mt < 2; mt++) {
                    mma_bf16(acc[mt][2 * ng],     aH[mt], bh[0], bh[1]);
                    mma_bf16(acc[mt][2 * ng],     aH[mt], bl[0], bl[1]);
                    mma_bf16(acc[mt][2 * ng],     aL[mt], bh[0], bh[1]);
                    mma_bf16(acc[mt][2 * ng + 1], aH[mt], bh[2], bh[3]);
                    mma_bf16(acc[mt][2 * ng + 1], aH[mt], bl[2], bl[3]);
                    mma_bf16(acc[mt][2 * ng + 1], aL[mt], bh[2], bh[3]);
                }
            }
        }
        __syncthreads();
    }

    // epilogue
    const int g  = lane >> 2;
    const int t4 = lane & 3;
#pragma unroll
    for (int mt = 0; mt < 2; mt++) {
        size_t row = blockRow + wm + mt * 16 + g;
#pragma unroll
        for (int nt = 0; nt < 8; nt++) {
            int col = blockN + wn + nt * 8 + t4 * 2;
            *(float2*)(C + row * 256 + col) =
                make_float2(acc[mt][nt][0], acc[mt][nt][1]);
            *(float2*)(C + (row + 8) * 256 + col) =
                make_float2(acc[mt][nt][2], acc[mt][nt][3]);
        }
    }

    if (!fuse) return;

    // ---- decoupled finisher: last of 26 blocks runs the jet combine ----
    __threadfence();                         // release C-tile writes
    __shared__ int s_last;
    if (tid == 0) s_last = (atomicAdd(&g_cnt[sgrp], 1) == 25);
    __syncthreads();
    if (!s_last) return;
    __threadfence();                         // acquire peers' C writes

    const size_t S4 = SLICE / 4;
    const size_t base4 = (size_t)sgrp * 8192;   // 128 samples * 64 quads
#pragma unroll 1
    for (int q = tid; q < 8192; q += 256) {
        size_t e4 = base4 + q;
        const int kb = (q & 63) * 4;

        float4 zq[13];
#pragma unroll
        for (int ch = 0; ch < 13; ch++)
            zq[ch] = ((const float4*)C)[ch * S4 + e4];

        float o[13][4];
#pragma unroll
        for (int j = 0; j < 4; j++) {
            float zh = ((const float*)&zq[0])[j] + bvec[kb + j];
            float zx = ((const float*)&zq[1])[j],  zy = ((const float*)&zq[2])[j];
            float zt = ((const float*)&zq[3])[j];
            float zxx = ((const float*)&zq[4])[j], zxy = ((const float*)&zq[5])[j];
            float zyy = ((const float*)&zq[6])[j], zxt = ((const float*)&zq[7])[j];
            float zyt = ((const float*)&zq[8])[j];
            float zxxx = ((const float*)&zq[9])[j],  zxxy = ((const float*)&zq[10])[j];
            float zxyy = ((const float*)&zq[11])[j], zyyy = ((const float*)&zq[12])[j];

            float h = tanhf(zh);
            float d = 1.0f - h * h;
            float hd2 = -2.0f * h * d;
            float c3 = (4.0f * h * h - 2.0f * d) * d;

            o[0][j] = h;
            o[1][j] = d * zx;
            o[2][j] = d * zy;
            o[3][j] = d * zt;
            o[4][j] = d * zxx + hd2 * zx * zx;
            o[5][j] = d * zxy + hd2 * zx * zy;
            o[6][j] = d * zyy + hd2 * zy * zy;
            o[7][j] = d * zxt + hd2 * zx * zt;
            o[8][j] = d * zyt + hd2 * zy * zt;
            o[9][j]  = d * zxxx + hd2 * 3.0f * zx * zxx + c3 * zx * zx * zx;
            o[10][j] = d * zxxy + hd2 * (zy * zxx + 2.0f * zx * zxy) + c3 * zx * zx * zy;
            o[11][j] = d * zxyy + hd2 * (2.0f * zy * zxy + zx * zyy) + c3 * zx * zy * zy;
            o[12][j] = d * zyyy + hd2 * 3.0f * zy * zyy + c3 * zy * zy * zy;
        }

#pragma unroll
        for (int ch = 0; ch < 13; ch++) {
            __nv_bfloat162 h0, h1, l0, l1;
            h0.x = trunc_bf(o[ch][0]); h0.y = trunc_bf(o[ch][1]);
            h1.x = trunc_bf(o[ch][2]); h1.y = trunc_bf(o[ch][3]);
            l0.x = __float2bfloat16(trunc_res(o[ch][0]));
            l0.y = __float2bfloat16(trunc_res(o[ch][1]));
            l1.x = __float2bfloat16(trunc_res(o[ch][2]));
            l1.y = __float2bfloat16(trunc_res(o[ch][3]));
            ((__nv_bfloat162*)hiO)[ch * (S4 * 2) + e4 * 2]     = h0;
            ((__nv_bfloat162*)hiO)[ch * (S4 * 2) + e4 * 2 + 1] = h1;
            ((__nv_bfloat162*)loO)[ch * (S4 * 2) + e4 * 2]     = l0;
            ((__nv_bfloat162*)loO)[ch * (S4 * 2) + e4 * 2 + 1] = l1;
        }
    }
    if (tid == 0) g_cnt[sgrp] = 0;   // reset for next fused GEMM launch
}

// ---------------------------------------------------------------------------
// Merged head reduction: blocks [0, NPTS/8) do the PDE head on Z (13ch),
// blocks [NPTS/8, 2*NPTS/8) do the data head on Zd (3ch). One warp/sample.
// ---------------------------------------------------------------------------
__global__ void head_reduce(const float* __restrict__ Z,
                            const float* __restrict__ Zd,
                            const float* __restrict__ bp1,
                            const float* __restrict__ Wp2,
                            const float* __restrict__ lam1p,
                            const float* __restrict__ lam2p,
                            const float* __restrict__ bd1,
                            const float* __restrict__ Wd2,
                            const float* __restrict__ bd2,
                            float* __restrict__ out) {
    const int NB = NPTS / 8;
    const int lane = threadIdx.x & 31;
    const size_t S = SLICE;

    if (blockIdx.x < NB) {
        int warp = (blockIdx.x * blockDim.x + threadIdx.x) >> 5;
        const size_t base = (size_t)warp * 256;

        float acc[14];
#pragma unroll
        for (int i = 0; i < 14; i++) acc[i] = 0.0f;

#pragma unroll
        for (int kk = lane; kk < 256; kk += 32) {
            size_t e = base + kk;
            float zh = Z[e] + bp1[kk];
            float h = tanhf(zh);
            float d = 1.0f - h * h;
            float zx = Z[S + e], zy = Z[2 * S + e], zt = Z[3 * S + e];
            float zxx = Z[4 * S + e], zxy = Z[5 * S + e], zyy = Z[6 * S + e];
            float zxt = Z[7 * S + e], zyt = Z[8 * S + e];
            float zxxx = Z[9 * S + e], zxxy = Z[10 * S + e];
            float zxyy = Z[11 * S + e], zyyy = Z[12 * S + e];
            float hd2 = -2.0f * h * d;
            float c3 = (4.0f * h * h - 2.0f * d) * d;

            float hx = d * zx, hy = d * zy, ht = d * zt;
            float hxx = d * zxx + hd2 * zx * zx;
            float hxy = d * zxy + hd2 * zx * zy;
            float hyy = d * zyy + hd2 * zy * zy;
            float hxt = d * zxt + hd2 * zx * zt;
            float hyt = d * zyt + hd2 * zy * zt;
            float hxxx = d * zxxx + hd2 * 3.0f * zx * zxx + c3 * zx * zx * zx;
            float hxxy = d * zxxy + hd2 * (zy * zxx + 2.0f * zx * zxy) + c3 * zx * zx * zy;
            float hxyy = d * zxyy + hd2 * (2.0f * zy * zxy + zx * zyy) + c3 * zx * zy * zy;
            float hyyy = d * zyyy + hd2 * 3.0f * zy * zyy + c3 * zy * zy * zy;

            float w0 = Wp2[kk];
            float w1 = Wp2[256 + kk];
            acc[0] += w0 * hx;   acc[1] += w0 * hy;   acc[2] += w0 * ht;
            acc[3] += w0 * hxx;  acc[4] += w0 * hxy;  acc[5] += w0 * hyy;
            acc[6] += w0 * hxt;  acc[7] += w0 * hyt;
            acc[8] += w0 * hxxx; acc[9] += w0 * hxxy;
            acc[10] += w0 * hxyy; acc[11] += w0 * hyyy;
            acc[12] += w1 * hx;  acc[13] += w1 * hy;
        }
#pragma unroll
        for (int i = 0; i < 14; i++)
#pragma unroll
            for (int o = 16; o; o >>= 1)
                acc[i] += __shfl_xor_sync(0xffffffffu, acc[i], o);

        if (lane == 0) {
            float lam1 = lam1p[0], lam2 = lam2p[0];
            float sx = acc[0], sy = acc[1];
            float sxx = acc[3], sxy = acc[4], syy = acc[5], sxt = acc[6], syt = acc[7];
            float sxxx = acc[8], sxxy = acc[9], sxyy = acc[10], syyy = acc[11];
            float px = acc[12], py = acc[13];
            float u = sy, v = -sx;
            float f = lam1 * (syt + u * sxy + v * syy) + px - lam2 * (sxxy + syyy);
            float g = lam1 * (-sxt + u * (-sxx) + v * (-sxy)) + py - lam2 * (-sxxx - sxyy);
            out[3 * NPTS + warp] = f;
            out[4 * NPTS + warp] = g;
        }
    } else {
        int warp = ((blockIdx.x - NB) * blockDim.x + threadIdx.x) >> 5;
        const size_t base = (size_t)warp * 256;
        float ap = 0.0f, au = 0.0f, av = 0.0f;
#pragma unroll
        for (int kk = lane; kk < 256; kk += 32) {
            size_t e = base + kk;
            float zh = Zd[e] + bd1[kk];
            float h = tanhf(zh);
            float d = 1.0f - h * h;
            float hx = d * Zd[S + e];
            float hy = d * Zd[2 * S + e];
            float w0 = Wd2[kk];
            float w1 = Wd2[256 + kk];
            ap += w1 * h;
            au += w0 * hy;
            av += w0 * hx;
        }
#pragma unroll
        for (int o = 16; o; o >>= 1) {
            ap += __shfl_xor_sync(0xffffffffu, ap, o);
            au += __shfl_xor_sync(0xffffffffu, au, o);
            av += __shfl_xor_sync(0xffffffffu, av, o);
        }
        if (lane == 0) {
            out[warp] = ap + bd2[1];
            out[NPTS + warp] = au;
            out[2 * NPTS + warp] = -av;
        }
    }
}

// ---------------------------------------------------------------------------
// Host launch
// ---------------------------------------------------------------------------
extern "C" void kernel_launch(void* const* d_in, const int* in_sizes, int n_in,
                              void* d_out, int out_size) {
    const float* x   = (const float*)d_in[0];
    const float* y   = (const float*)d_in[1];
    const float* t   = (const float*)d_in[2];
    const float* W1  = (const float*)d_in[6];
    const float* b1  = (const float*)d_in[7];
    const float* W2  = (const float*)d_in[8];
    const float* b2  = (const float*)d_in[9];
    const float* W3  = (const float*)d_in[10];
    const float* b3  = (const float*)d_in[11];
    const float* Wp1 = (const float*)d_in[12];
    const float* bp1 = (const float*)d_in[13];
    const float* Wp2 = (const float*)d_in[14];
    const float* Wd1 = (const float*)d_in[16];
    const float* bd1 = (const float*)d_in[17];
    const float* Wd2 = (const float*)d_in[18];
    const float* bd2 = (const float*)d_in[19];
    const float* lam1 = (const float*)d_in[20];
    const float* lam2 = (const float*)d_in[21];
    float* out = (float*)d_out;

    float *C = nullptr, *Cd = nullptr;
    __nv_bfloat16 *hiA, *loA, *hiB, *loB, *Whi, *Wlo;
    cudaGetSymbolAddress((void**)&C,   g_C);
    cudaGetSymbolAddress((void**)&Cd,  g_Cd);
    cudaGetSymbolAddress((void**)&hiA, g_hiA);
    cudaGetSymbolAddress((void**)&loA, g_loA);
    cudaGetSymbolAddress((void**)&hiB, g_hiB);
    cudaGetSymbolAddress((void**)&loB, g_loB);
    cudaGetSymbolAddress((void**)&Whi, g_Whi);
    cudaGetSymbolAddress((void**)&Wlo, g_Wlo);

    static bool attr_set = false;
    if (!attr_set) {
        cudaFuncSetAttribute(gemm_v3, cudaFuncAttributeMaxDynamicSharedMemorySize, SMSZ);
        attr_set = true;
    }

    const int NH = NPTS * HID;
    const int M13_T = NCH * NPTS / 128;   // 6656
    const int M3_T  = 3 * NPTS / 128;     // 1536
    const int WOFF = 256 * 256;

    wconv_kernel<<<(4 * 65536) / 256, 256>>>(W2, W3, Wp1, Wd1);
    layer1_kernel<<<NH / 256, 256>>>(x, y, t, W1, b1);

    // Layer 2 (GEMM + fused combine -> hiB/loB)
    gemm_v3<<<dim3(M13_T, 2), 256, SMSZ>>>(hiA, loA,
        Whi + 0 * WOFF, Wlo + 0 * WOFF, C,
        Whi + 0 * WOFF, Wlo + 0 * WOFF, C, M13_T,
        1, b2, hiB, loB);

    // Layer 3 (GEMM + fused combine -> hiA/loA)
    gemm_v3<<<dim3(M13_T, 2), 256, SMSZ>>>(hiB, loB,
        Whi + 1 * WOFF, Wlo + 1 * WOFF, C,
        Whi + 1 * WOFF, Wlo + 1 * WOFF, C, M13_T,
        1, b3, hiA, loA);

    // Merged heads: PDE (13ch -> C) + data (3ch -> Cd) in one launch, no fuse
    gemm_v3<<<dim3(M13_T + M3_T, 2), 256, SMSZ>>>(hiA, loA,
        Whi + 2 * WOFF, Wlo + 2 * WOFF, C,
        Whi + 3 * WOFF, Wlo + 3 * WOFF, Cd, M13_T,
        0, b2, hiB, loB);

    // Merged reductions
    head_reduce<<<2 * (NPTS / 8), 256>>>(C, Cd, bp1, Wp2, lam1, lam2,
                                         bd1, Wd2, bd2, out);
}

// round 8
// speedup vs baseline: 1.0279x; 1.0279x over previous
#include <cuda_runtime.h>
#include <cuda_bf16.h>
#include <cstdint>

#define NPTS 65536
#define HID  256
#define SLICE ((size_t)NPTS * HID)
#define NCH  13

// fp32 GEMM-output buffers and bf16 hi/lo split activation buffers
static __device__ float          g_C  [(size_t)NCH * NPTS * HID];
static __device__ float          g_Cd [(size_t)3 * NPTS * HID];
static __device__ __nv_bfloat16  g_hiA[(size_t)NCH * NPTS * HID];
static __device__ __nv_bfloat16  g_loA[(size_t)NCH * NPTS * HID];
static __device__ __nv_bfloat16  g_hiB[(size_t)NCH * NPTS * HID];
static __device__ __nv_bfloat16  g_loB[(size_t)NCH * NPTS * HID];
// weight splits: slot 0=W2, 1=W3, 2=Wp1, 3=Wd1
static __device__ __nv_bfloat16  g_Whi[4 * 256 * 256];
static __device__ __nv_bfloat16  g_Wlo[4 * 256 * 256];

// ---------------------------------------------------------------------------
// hi = truncate-to-bf16(f), lo = RN-bf16(f - hi)
// ---------------------------------------------------------------------------
__device__ __forceinline__ void store_hl(__nv_bfloat16* __restrict__ hi,
                                         __nv_bfloat16* __restrict__ lo,
                                         size_t idx, float f) {
    unsigned u = __float_as_uint(f);
    float h = __uint_as_float(u & 0xFFFF0000u);
    hi[idx] = __ushort_as_bfloat16((unsigned short)(u >> 16));
    lo[idx] = __float2bfloat16(f - h);
}

__global__ void wconv_kernel(const float* __restrict__ w2,
                             const float* __restrict__ w3,
                             const float* __restrict__ wp1,
                             const float* __restrict__ wd1) {
    int e = blockIdx.x * blockDim.x + threadIdx.x;
    if (e >= 4 * 65536) return;
    int m = e >> 16;
    int l = e & 65535;
    const float* src = (m == 0) ? w2 : (m == 1) ? w3 : (m == 2) ? wp1 : wd1;
    store_hl(g_Whi, g_Wlo, (size_t)e, src[l]);
}

__global__ void layer1_kernel(const float* __restrict__ x,
                              const float* __restrict__ y,
                              const float* __restrict__ t,
                              const float* __restrict__ W1,
                              const float* __restrict__ b1) {
    int e = blockIdx.x * blockDim.x + threadIdx.x;
    if (e >= NPTS * HID) return;
    int n = e >> 8;
    int k = e & 255;
    float cx = W1[k * 3 + 0];
    float cy = W1[k * 3 + 1];
    float ct = W1[k * 3 + 2];
    float z = cx * x[n] + cy * y[n] + ct * t[n] + b1[k];
    float h = tanhf(z);
    float d = 1.0f - h * h;
    const size_t S = SLICE;
    store_hl(g_hiA, g_loA, e, h);
    store_hl(g_hiA, g_loA, S * 1 + e, d * cx);
    store_hl(g_hiA, g_loA, S * 2 + e, d * cy);
    store_hl(g_hiA, g_loA, S * 3 + e, d * ct);
    float m2 = -2.0f * h * d;
    store_hl(g_hiA, g_loA, S * 4 + e, m2 * cx * cx);
    store_hl(g_hiA, g_loA, S * 5 + e, m2 * cx * cy);
    store_hl(g_hiA, g_loA, S * 6 + e, m2 * cy * cy);
    store_hl(g_hiA, g_loA, S * 7 + e, m2 * cx * ct);
    store_hl(g_hiA, g_loA, S * 8 + e, m2 * cy * ct);
    float m3 = d * (6.0f * h * h - 2.0f);
    store_hl(g_hiA, g_loA, S * 9 + e,  m3 * cx * cx * cx);
    store_hl(g_hiA, g_loA, S * 10 + e, m3 * cx * cx * cy);
    store_hl(g_hiA, g_loA, S * 11 + e, m3 * cx * cy * cy);
    store_hl(g_hiA, g_loA, S * 12 + e, m3 * cy * cy * cy);
}

// ---------------------------------------------------------------------------
// Tensor-core GEMM (NT), C[m,n] = sum_k A[m,k]*W[n,k], K = N = 256.
// Block tile 128x128, 8 warps (32x64 warp tile), K-chunk 32.
// 3-stage cp.async ring, ONE __syncthreads per chunk.
// smem row = 128B: [hi 64B | lo 64B], XOR-swizzled 16B chunks (c ^ (row&7)).
// Accum Ah*Wh + Ah*Wl + Al*Wh (fp32). Second job appended via nbig.
// ---------------------------------------------------------------------------
#define STGB  32768            // per-stage bytes: A 16K + W 16K
#define SMSZ  (3 * STGB)       // 98304

#define LDSM4(R, addr) \
    asm volatile("ldmatrix.sync.aligned.m8n8.x4.shared.b16 {%0,%1,%2,%3}, [%4];" \
                 : "=r"((R)[0]), "=r"((R)[1]), "=r"((R)[2]), "=r"((R)[3]) \
                 : "r"(addr))
#define CPA(dst, src) \
    asm volatile("cp.async.cg.shared.global [%0], [%1], 16;" :: "r"(dst), "l"(src))
#define CPC() asm volatile("cp.async.commit_group;")
#define CPW1() asm volatile("cp.async.wait_group 1;" ::: "memory")
#define CPW0() asm volatile("cp.async.wait_group 0;" ::: "memory")

__device__ __forceinline__ void mma_bf16(float* c, const unsigned* a,
                                         unsigned b0, unsigned b1) {
    asm volatile(
        "mma.sync.aligned.m16n8k16.row.col.f32.bf16.bf16.f32 "
        "{%0,%1,%2,%3}, {%4,%5,%6,%7}, {%8,%9}, {%0,%1,%2,%3};"
        : "+f"(c[0]), "+f"(c[1]), "+f"(c[2]), "+f"(c[3])
        : "r"(a[0]), "r"(a[1]), "r"(a[2]), "r"(a[3]), "r"(b0), "r"(b1));
}

__global__ void __launch_bounds__(256, 2)
gemm_v8(const __nv_bfloat16* __restrict__ Ahi,
        const __nv_bfloat16* __restrict__ Alo,
        const __nv_bfloat16* Whi_, const __nv_bfloat16* Wlo_, float* C_,
        const __nv_bfloat16* Whi2_, const __nv_bfloat16* Wlo2_, float* C2_,
        int nbig) {
    extern __shared__ __align__(128) unsigned char sm[];
    const unsigned sb = (unsigned)__cvta_generic_to_shared(sm);

    int bx = blockIdx.x;
    const __nv_bfloat16* Whi = Whi_;
    const __nv_bfloat16* Wlo = Wlo_;
    float* C = C_;
    if (bx >= nbig) {            // appended second job (data head)
        bx -= nbig;
        Whi = Whi2_;
        Wlo = Wlo2_;
        C = C2_;
    }

    const int tid  = threadIdx.x;
    const int lane = tid & 31;
    const int warp = tid >> 5;
    const int wm   = (warp & 3) * 32;
    const int wn   = (warp >> 2) * 64;

    const size_t blockRow = (size_t)bx * 128;
    const int    blockN   = blockIdx.y * 128;

    // loader: 2 threads per row; each covers 2 hi chunks + 2 lo chunks per array
    const int lr = tid >> 1;          // row 0..127
    const int lc = (tid & 1) * 2;     // hi chunk base 0 or 2
    const unsigned sw = (unsigned)(lr & 7);
    const __nv_bfloat16* gAh = Ahi + (blockRow + lr) * 256;
    const __nv_bfloat16* gAl = Alo + (blockRow + lr) * 256;
    const __nv_bfloat16* gWh = Whi + (size_t)(blockN + lr) * 256;
    const __nv_bfloat16* gWl = Wlo + (size_t)(blockN + lr) * 256;
    const unsigned aDst = sb + lr * 128;
    const unsigned wDst = sb + 16384 + lr * 128;

    float acc[2][8][4];
#pragma unroll
    for (int i = 0; i < 2; i++)
#pragma unroll
        for (int j = 0; j < 8; j++)
#pragma unroll
            for (int l = 0; l < 4; l++) acc[i][j][l] = 0.0f;

#define ISSUE(kc) do {                                                         \
        const int _s = (kc) % 3;                                               \
        const int _ko = (kc) * 32;                                             \
        unsigned _a = aDst + _s * STGB;                                        \
        unsigned _w = wDst + _s * STGB;                                        \
        CPA(_a + ((unsigned)((lc    ) ^ sw) << 4), gAh + _ko + lc * 8);        \
        CPA(_a + ((unsigned)((lc + 1) ^ sw) << 4), gAh + _ko + lc * 8 + 8);    \
        CPA(_a + ((unsigned)((lc + 4) ^ sw) << 4), gAl + _ko + lc * 8);        \
        CPA(_a + ((unsigned)((lc + 5) ^ sw) << 4), gAl + _ko + lc * 8 + 8);    \
        CPA(_w + ((unsigned)((lc    ) ^ sw) << 4), gWh + _ko + lc * 8);        \
        CPA(_w + ((unsigned)((lc + 1) ^ sw) << 4), gWh + _ko + lc * 8 + 8);    \
        CPA(_w + ((unsigned)((lc + 4) ^ sw) << 4), gWl + _ko + lc * 8);        \
        CPA(_w + ((unsigned)((lc + 5) ^ sw) << 4), gWl + _ko + lc * 8 + 8);    \
        CPC();                                                                 \
    } while (0)

    ISSUE(0);
    ISSUE(1);

    // fragment address components
    const int arow  = wm + (lane & 15);                      // + mt*16
    const int acsel = lane >> 4;                             // 0/1
    const int brow  = wn + (lane & 7) + ((lane >> 4) << 3);  // + ng*16
    const int bcsel = (lane >> 3) & 1;

#pragma unroll 1
    for (int kc = 0; kc < 8; kc++) {
        if (kc < 7) { CPW1(); } else { CPW0(); }
        __syncthreads();
        if (kc < 6) ISSUE(kc + 2);          // safe: that stage was read at kc-1

        const unsigned s0 = sb + (kc % 3) * STGB;
#pragma unroll
        for (int step = 0; step < 2; step++) {
            unsigned aH[2][4], aL[2][4];
            const int cA = step * 2 + acsel;
#pragma unroll
            for (int mt = 0; mt < 2; mt++) {
                const int row = arow + mt * 16;
                const unsigned rs = (unsigned)(row & 7);
                const unsigned ab = s0 + row * 128;
                LDSM4(aH[mt], ab + ((unsigned)(cA ^ rs) << 4));
                LDSM4(aL[mt], ab + ((unsigned)((cA + 4) ^ rs) << 4));
            }
            const int cB = step * 2 + bcsel;
#pragma unroll
            for (int ng = 0; ng < 4; ng++) {
                const int rowb = brow + ng * 16;
                const unsigned rbs = (unsigned)(rowb & 7);
                const unsigned bb = s0 + 16384 + rowb * 128;
                unsigned bh[4], bl[4];
                LDSM4(bh, bb + ((unsigned)(cB ^ rbs) << 4));
                LDSM4(bl, bb + ((unsigned)((cB + 4) ^ rbs) << 4));
#pragma unroll
                for (int mt = 0; mt < 2; mt++) {
                    mma_bf16(acc[mt][2 * ng],     aH[mt], bh[0], bh[1]);
                    mma_bf16(acc[mt][2 * ng],     aH[mt], bl[0], bl[1]);
                    mma_bf16(acc[mt][2 * ng],     aL[mt], bh[0], bh[1]);
                    mma_bf16(acc[mt][2 * ng + 1], aH[mt], bh[2], bh[3]);
                    mma_bf16(acc[mt][2 * ng + 1], aH[mt], bl[2], bl[3]);
                    mma_bf16(acc[mt][2 * ng + 1], aL[mt], bh[2], bh[3]);
                }
            }
        }
    }

    // epilogue
    const int g  = lane >> 2;
    const int t4 = lane & 3;
#pragma unroll
    for (int mt = 0; mt < 2; mt++) {
        size_t row = blockRow + wm + mt * 16 + g;
#pragma unroll
        for (int nt = 0; nt < 8; nt++) {
            int col = blockN + wn + nt * 8 + t4 * 2;
            *(float2*)(C + row * 256 + col) =
                make_float2(acc[mt][nt][0], acc[mt][nt][1]);
            *(float2*)(C + (row + 8) * 256 + col) =
                make_float2(acc[mt][nt][2], acc[mt][nt][3]);
        }
    }
}

// ---------------------------------------------------------------------------
// Pointwise tanh jet propagation: reads fp32 Z (= g_C), writes hi/lo bf16.
// ---------------------------------------------------------------------------
__global__ void combine_kernel(const float* __restrict__ Z,
                               const float* __restrict__ b,
                               __nv_bfloat16* __restrict__ hi,
                               __nv_bfloat16* __restrict__ lo) {
    int e = blockIdx.x * blockDim.x + threadIdx.x;
    if (e >= NPTS * HID) return;
    int k = e & 255;
    const size_t S = SLICE;
    float zh = Z[e] + b[k];
    float zx = Z[S + e], zy = Z[2 * S + e], zt = Z[3 * S + e];
    float zxx = Z[4 * S + e], zxy = Z[5 * S + e], zyy = Z[6 * S + e];
    float zxt = Z[7 * S + e], zyt = Z[8 * S + e];
    float zxxx = Z[9 * S + e], zxxy = Z[10 * S + e];
    float zxyy = Z[11 * S + e], zyyy = Z[12 * S + e];

    float h = tanhf(zh);
    float d = 1.0f - h * h;
    float hd2 = -2.0f * h * d;
    float c3 = (4.0f * h * h - 2.0f * d) * d;

    store_hl(hi, lo, e, h);
    store_hl(hi, lo, S + e, d * zx);
    store_hl(hi, lo, 2 * S + e, d * zy);
    store_hl(hi, lo, 3 * S + e, d * zt);
    store_hl(hi, lo, 4 * S + e, d * zxx + hd2 * zx * zx);
    store_hl(hi, lo, 5 * S + e, d * zxy + hd2 * zx * zy);
    store_hl(hi, lo, 6 * S + e, d * zyy + hd2 * zy * zy);
    store_hl(hi, lo, 7 * S + e, d * zxt + hd2 * zx * zt);
    store_hl(hi, lo, 8 * S + e, d * zyt + hd2 * zy * zt);
    store_hl(hi, lo, 9 * S + e,  d * zxxx + hd2 * 3.0f * zx * zxx + c3 * zx * zx * zx);
    store_hl(hi, lo, 10 * S + e, d * zxxy + hd2 * (zy * zxx + 2.0f * zx * zxy) + c3 * zx * zx * zy);
    store_hl(hi, lo, 11 * S + e, d * zxyy + hd2 * (2.0f * zy * zxy + zx * zyy) + c3 * zx * zy * zy);
    store_hl(hi, lo, 12 * S + e, d * zyyy + hd2 * 3.0f * zy * zyy + c3 * zy * zy * zy);
}

// ---------------------------------------------------------------------------
// Merged head reduction: blocks [0, NPTS/8) do the PDE head on Z (13ch),
// blocks [NPTS/8, 2*NPTS/8) do the data head on Zd (3ch). One warp/sample.
// ---------------------------------------------------------------------------
__global__ void head_reduce(const float* __restrict__ Z,
                            const float* __restrict__ Zd,
                            const float* __restrict__ bp1,
                            const float* __restrict__ Wp2,
                            const float* __restrict__ lam1p,
                            const float* __restrict__ lam2p,
                            const float* __restrict__ bd1,
                            const float* __restrict__ Wd2,
                            const float* __restrict__ bd2,
                            float* __restrict__ out) {
    const int NB = NPTS / 8;
    const int lane = threadIdx.x & 31;
    const size_t S = SLICE;

    if (blockIdx.x < NB) {
        int warp = (blockIdx.x * blockDim.x + threadIdx.x) >> 5;
        const size_t base = (size_t)warp * 256;

        float acc[14];
#pragma unroll
        for (int i = 0; i < 14; i++) acc[i] = 0.0f;

#pragma unroll
        for (int kk = lane; kk < 256; kk += 32) {
            size_t e = base + kk;
            float zh = Z[e] + bp1[kk];
            float h = tanhf(zh);
            float d = 1.0f - h * h;
            float zx = Z[S + e], zy = Z[2 * S + e], zt = Z[3 * S + e];
            float zxx = Z[4 * S + e], zxy = Z[5 * S + e], zyy = Z[6 * S + e];
            float zxt = Z[7 * S + e], zyt = Z[8 * S + e];
            float zxxx = Z[9 * S + e], zxxy = Z[10 * S + e];
            float zxyy = Z[11 * S + e], zyyy = Z[12 * S + e];
            float hd2 = -2.0f * h * d;
            float c3 = (4.0f * h * h - 2.0f * d) * d;

            float hx = d * zx, hy = d * zy, ht = d * zt;
            float hxx = d * zxx + hd2 * zx * zx;
            float hxy = d * zxy + hd2 * zx * zy;
            float hyy = d * zyy + hd2 * zy * zy;
            float hxt = d * zxt + hd2 * zx * zt;
            float hyt = d * zyt + hd2 * zy * zt;
            float hxxx = d * zxxx + hd2 * 3.0f * zx * zxx + c3 * zx * zx * zx;
            float hxxy = d * zxxy + hd2 * (zy * zxx + 2.0f * zx * zxy) + c3 * zx * zx * zy;
            float hxyy = d * zxyy + hd2 * (2.0f * zy * zxy + zx * zyy) + c3 * zx * zy * zy;
            float hyyy = d * zyyy + hd2 * 3.0f * zy * zyy + c3 * zy * zy * zy;

            float w0 = Wp2[kk];
            float w1 = Wp2[256 + kk];
            acc[0] += w0 * hx;   acc[1] += w0 * hy;   acc[2] += w0 * ht;
            acc[3] += w0 * hxx;  acc[4] += w0 * hxy;  acc[5] += w0 * hyy;
            acc[6] += w0 * hxt;  acc[7] += w0 * hyt;
            acc[8] += w0 * hxxx; acc[9] += w0 * hxxy;
            acc[10] += w0 * hxyy; acc[11] += w0 * hyyy;
            acc[12] += w1 * hx;  acc[13] += w1 * hy;
        }
#pragma unroll
        for (int i = 0; i < 14; i++)
#pragma unroll
            for (int o = 16; o; o >>= 1)
                acc[i] += __shfl_xor_sync(0xffffffffu, acc[i], o);

        if (lane == 0) {
            float lam1 = lam1p[0], lam2 = lam2p[0];
            float sx = acc[0], sy = acc[1];
            float sxx = acc[3], sxy = acc[4], syy = acc[5], sxt = acc[6], syt = acc[7];
            float sxxx = acc[8], sxxy = acc[9], sxyy = acc[10], syyy = acc[11];
            float px = acc[12], py = acc[13];
            float u = sy, v = -sx;
            float f = lam1 * (syt + u * sxy + v * syy) + px - lam2 * (sxxy + syyy);
            float g = lam1 * (-sxt + u * (-sxx) + v * (-sxy)) + py - lam2 * (-sxxx - sxyy);
            out[3 * NPTS + warp] = f;
            out[4 * NPTS + warp] = g;
        }
    } else {
        int warp = ((blockIdx.x - NB) * blockDim.x + threadIdx.x) >> 5;
        const size_t base = (size_t)warp * 256;
        float ap = 0.0f, au = 0.0f, av = 0.0f;
#pragma unroll
        for (int kk = lane; kk < 256; kk += 32) {
            size_t e = base + kk;
            float zh = Zd[e] + bd1[kk];
            float h = tanhf(zh);
            float d = 1.0f - h * h;
            float hx = d * Zd[S + e];
            float hy = d * Zd[2 * S + e];
            float w0 = Wd2[kk];
            float w1 = Wd2[256 + kk];
            ap += w1 * h;
            au += w0 * hy;
            av += w0 * hx;
        }
#pragma unroll
        for (int o = 16; o; o >>= 1) {
            ap += __shfl_xor_sync(0xffffffffu, ap, o);
            au += __shfl_xor_sync(0xffffffffu, au, o);
            av += __shfl_xor_sync(0xffffffffu, av, o);
        }
        if (lane == 0) {
            out[warp] = ap + bd2[1];
            out[NPTS + warp] = au;
            out[2 * NPTS + warp] = -av;
        }
    }
}

// ---------------------------------------------------------------------------
// Host launch
// ---------------------------------------------------------------------------
extern "C" void kernel_launch(void* const* d_in, const int* in_sizes, int n_in,
                              void* d_out, int out_size) {
    const float* x   = (const float*)d_in[0];
    const float* y   = (const float*)d_in[1];
    const float* t   = (const float*)d_in[2];
    const float* W1  = (const float*)d_in[6];
    const float* b1  = (const float*)d_in[7];
    const float* W2  = (const float*)d_in[8];
    const float* b2  = (const float*)d_in[9];
    const float* W3  = (const float*)d_in[10];
    const float* b3  = (const float*)d_in[11];
    const float* Wp1 = (const float*)d_in[12];
    const float* bp1 = (const float*)d_in[13];
    const float* Wp2 = (const float*)d_in[14];
    const float* Wd1 = (const float*)d_in[16];
    const float* bd1 = (const float*)d_in[17];
    const float* Wd2 = (const float*)d_in[18];
    const float* bd2 = (const float*)d_in[19];
    const float* lam1 = (const float*)d_in[20];
    const float* lam2 = (const float*)d_in[21];
    float* out = (float*)d_out;

    float *C = nullptr, *Cd = nullptr;
    __nv_bfloat16 *hiA, *loA, *hiB, *loB, *Whi, *Wlo;
    cudaGetSymbolAddress((void**)&C,   g_C);
    cudaGetSymbolAddress((void**)&Cd,  g_Cd);
    cudaGetSymbolAddress((void**)&hiA, g_hiA);
    cudaGetSymbolAddress((void**)&loA, g_loA);
    cudaGetSymbolAddress((void**)&hiB, g_hiB);
    cudaGetSymbolAddress((void**)&loB, g_loB);
    cudaGetSymbolAddress((void**)&Whi, g_Whi);
    cudaGetSymbolAddress((void**)&Wlo, g_Wlo);

    static bool attr_set = false;
    if (!attr_set) {
        cudaFuncSetAttribute(gemm_v8, cudaFuncAttributeMaxDynamicSharedMemorySize, SMSZ);
        attr_set = true;
    }

    const int NH = NPTS * HID;
    const int M13_T = NCH * NPTS / 128;   // 6656
    const int M3_T  = 3 * NPTS / 128;     // 1536
    const int WOFF = 256 * 256;

    wconv_kernel<<<(4 * 65536) / 256, 256>>>(W2, W3, Wp1, Wd1);
    layer1_kernel<<<NH / 256, 256>>>(x, y, t, W1, b1);

    // Layer 2
    gemm_v8<<<dim3(M13_T, 2), 256, SMSZ>>>(hiA, loA,
        Whi + 0 * WOFF, Wlo + 0 * WOFF, C,
        Whi + 0 * WOFF, Wlo + 0 * WOFF, C, M13_T);
    combine_kernel<<<NH / 256, 256>>>(C, b2, hiB, loB);

    // Layer 3
    gemm_v8<<<dim3(M13_T, 2), 256, SMSZ>>>(hiB, loB,
        Whi + 1 * WOFF, Wlo + 1 * WOFF, C,
        Whi + 1 * WOFF, Wlo + 1 * WOFF, C, M13_T);
    combine_kernel<<<NH / 256, 256>>>(C, b3, hiA, loA);

    // Merged heads: PDE (13ch -> C) + data (3ch -> Cd) in one launch
    gemm_v8<<<dim3(M13_T + M3_T, 2), 256, SMSZ>>>(hiA, loA,
        Whi + 2 * WOFF, Wlo + 2 * WOFF, C,
        Whi + 3 * WOFF, Wlo + 3 * WOFF, Cd, M13_T);

    // Merged reductions
    head_reduce<<<2 * (NPTS / 8), 256>>>(C, Cd, bp1, Wp2, lam1, lam2,
                                         bd1, Wd2, bd2, out);
}